// round 11
// baseline (speedup 1.0000x reference)
#include <cuda_runtime.h>
#include <cuda_fp16.h>

// SimpleGraphHead fused kernel, round 11.
// B=128, N=64, cl=64. One CTA per batch, 14 warps (448 thr, ~144 regs).
// M=32 slabs, K-split output-stationary GEMM1, f16-acc mma throughout.
// 128 slabs / 14 warps -> critical path 10 slabs (vs 11 at 12 warps).

#define NWARPS 14
#define NTHREADS 448

struct Smem {
    float  H[64][64];        // fp32 state-encoder output (for hx/hy + Hh src)
    __half Hh[64][72];       // fp16 H, row=144B (persistent; A operand)
    __half P1h[64][136];     // row=272B
    __half P2h[64][136];
    __half Q1h[64][72];      // row=144B
    __half Q2h[64][72];
    __half W2T[128][136];    // overlay region starts here (88 KB)
    __half W3T[128][136];
    __half AW2T[128][72];
    __half w1Lh[128];
    __half aw1Lh[64];
    __half2 b2h2[64];
    __half2 b3h2[64];
    __half2 abh2[64];        // 0.5*an_b2 pairs
    float  hx[64], hy[64];
    float  accs[128];
    float  msum[128];
};

__device__ __forceinline__ __half2 u2h(unsigned u) {
    return *reinterpret_cast<__half2*>(&u);
}
__device__ __forceinline__ unsigned h2u(__half2 h) {
    return *reinterpret_cast<unsigned*>(&h);
}
__device__ __forceinline__ unsigned tanh_h2(unsigned x) {
    unsigned y;
    asm("tanh.approx.f16x2 %0, %1;" : "=r"(y) : "r"(x));
    return y;
}
// f16-accumulate mma
__device__ __forceinline__ void mma16816h(unsigned* d, const unsigned* a,
                                          unsigned b0, unsigned b1) {
    asm volatile(
        "mma.sync.aligned.m16n8k16.row.col.f16.f16.f16.f16 "
        "{%0,%1}, {%2,%3,%4,%5}, {%6,%7}, {%0,%1};\n"
        : "+r"(d[0]), "+r"(d[1])
        : "r"(a[0]), "r"(a[1]), "r"(a[2]), "r"(a[3]), "r"(b0), "r"(b1));
}
// f32-accumulate mma (for table builds)
__device__ __forceinline__ void mma16816f(float* d, const unsigned* a,
                                          unsigned b0, unsigned b1) {
    asm volatile(
        "mma.sync.aligned.m16n8k16.row.col.f32.f16.f16.f32 "
        "{%0,%1,%2,%3}, {%4,%5,%6,%7}, {%8,%9}, {%0,%1,%2,%3};\n"
        : "+f"(d[0]), "+f"(d[1]), "+f"(d[2]), "+f"(d[3])
        : "r"(a[0]), "r"(a[1]), "r"(a[2]), "r"(a[3]), "r"(b0), "r"(b1));
}
__device__ __forceinline__ void ldm_x4(unsigned& r0, unsigned& r1,
                                       unsigned& r2, unsigned& r3,
                                       unsigned saddr) {
    asm volatile("ldmatrix.sync.aligned.m8n8.x4.shared.b16 {%0,%1,%2,%3}, [%4];"
                 : "=r"(r0), "=r"(r1), "=r"(r2), "=r"(r3) : "r"(saddr));
}
__device__ __forceinline__ unsigned frag_fix(unsigned p2f, unsigned d2,
                                             unsigned w, unsigned base,
                                             __half2 z2) {
    __half2 corr = __hfma2(u2h(d2), u2h(w), u2h(base));
    return h2u(__hmax2(__hadd2(u2h(p2f), corr), z2));
}
__device__ __forceinline__ unsigned relu_bias(unsigned acc, __half2 bias,
                                              __half2 z2) {
    return h2u(__hmax2(__hadd2(u2h(acc), bias), z2));
}
// sigmoid(da + ab) = 0.5*tanh(0.5*da + 0.5*ab) + 0.5, all half2
__device__ __forceinline__ __half2 sigmoid_h2(unsigned da, __half2 abp,
                                              __half2 h05) {
    unsigned t = h2u(__hfma2(u2h(da), h05, abp));
    return __hfma2(u2h(tanh_h2(t)), h05, h05);
}

__global__ void __launch_bounds__(NTHREADS, 1)
sgh_kernel(const float* __restrict__ s,
           const float* __restrict__ se_w1, const float* __restrict__ se_b1,
           const float* __restrict__ se_w2, const float* __restrict__ se_b2,
           const float* __restrict__ sd_w1, const float* __restrict__ sd_b1,
           const float* __restrict__ sd_w2, const float* __restrict__ sd_b2,
           const float* __restrict__ rc_w1, const float* __restrict__ rc_b1,
           const float* __restrict__ rc_w2, const float* __restrict__ rc_b2,
           const float* __restrict__ rc_w3, const float* __restrict__ rc_b3,
           const float* __restrict__ an_w1, const float* __restrict__ an_b1,
           const float* __restrict__ an_w2, const float* __restrict__ an_b2,
           float* __restrict__ out) {
    extern __shared__ char smraw[];
    Smem* sm = reinterpret_cast<Smem*>(smraw);
    const int b = blockIdx.x;
    const int tid = threadIdx.x;
    const int warp = tid >> 5;
    const int lane = tid & 31;
    const int g  = lane >> 2;
    const int t4 = lane & 3;
    const int trow = lane & 7;
    const int tileid = lane >> 3;
    const int lrow  = lane & 15;
    const int lcol8 = (lane >> 4) << 3;

    // Overlay region (88 KB spanning W2T/W3T/AW2T)
    char* ovl = reinterpret_cast<char*>(&sm->W2T[0][0]);
    float* T1    = reinterpret_cast<float*>(ovl);            // 16 KB
    float* Stile = reinterpret_cast<float*>(&sm->W3T[0][0]); // 16 KB
    __half* W1aT  = reinterpret_cast<__half*>(ovl);          // [128][72]
    __half* W1bT  = reinterpret_cast<__half*>(ovl + 18432);  // [128][72]
    __half* AW1aT = reinterpret_cast<__half*>(ovl + 36864);  // [64][72]
    __half* AW1bT = reinterpret_cast<__half*>(ovl + 46080);  // [64][72]

    // ---------------- Phase A: state encoder (fp32 scalar) ----------------
    const float* sb = s + (size_t)b * 64 * 64;
    for (int idx = tid; idx < 4096; idx += NTHREADS) Stile[idx] = sb[idx];
    __syncthreads();

    for (int ch = tid; ch < 64 * 16; ch += NTHREADS) {
        int r = ch >> 4, c0 = (ch & 15) << 2;
        const float* sr = &Stile[r * 64];
        float4 bb = *reinterpret_cast<const float4*>(se_b1 + c0);
        float a0 = bb.x, a1 = bb.y, a2 = bb.z, a3 = bb.w;
        #pragma unroll 8
        for (int k = 0; k < 64; k++) {
            float v = sr[k];
            float4 w = *reinterpret_cast<const float4*>(se_w1 + k * 64 + c0);
            a0 += v * w.x; a1 += v * w.y; a2 += v * w.z; a3 += v * w.w;
        }
        float* dst = &T1[r * 64 + c0];
        dst[0] = fmaxf(a0, 0.f); dst[1] = fmaxf(a1, 0.f);
        dst[2] = fmaxf(a2, 0.f); dst[3] = fmaxf(a3, 0.f);
    }
    __syncthreads();

    for (int ch = tid; ch < 64 * 16; ch += NTHREADS) {
        int r = ch >> 4, c0 = (ch & 15) << 2;
        const float* tr = &T1[r * 64];
        float4 bb = *reinterpret_cast<const float4*>(se_b2 + c0);
        float a0 = bb.x, a1 = bb.y, a2 = bb.z, a3 = bb.w;
        #pragma unroll 8
        for (int k = 0; k < 64; k++) {
            float v = tr[k];
            float4 w = *reinterpret_cast<const float4*>(se_w2 + k * 64 + c0);
            a0 += v * w.x; a1 += v * w.y; a2 += v * w.z; a3 += v * w.w;
        }
        sm->H[r][c0 + 0] = fmaxf(a0, 0.f); sm->H[r][c0 + 1] = fmaxf(a1, 0.f);
        sm->H[r][c0 + 2] = fmaxf(a2, 0.f); sm->H[r][c0 + 3] = fmaxf(a3, 0.f);
    }
    __syncthreads();

    // ---------------- Stage Hh + W1 tables (overlay) + misc ----------------
    if (tid < 64) { sm->hx[tid] = sm->H[tid][0]; sm->hy[tid] = sm->H[tid][1]; }
    if (tid < 128) {
        sm->w1Lh[tid] = __float2half(rc_w1[128 * 128 + tid]);
        sm->accs[tid] = 0.f;
        sm->msum[tid] = 0.f;
    }
    if (tid < 64) {
        sm->aw1Lh[tid] = __float2half(an_w1[128 * 64 + tid]);
        sm->b2h2[tid] = __floats2half2_rn(rc_b2[2 * tid], rc_b2[2 * tid + 1]);
        sm->b3h2[tid] = __floats2half2_rn(rc_b3[2 * tid], rc_b3[2 * tid + 1]);
        sm->abh2[tid] = __floats2half2_rn(0.5f * an_b2[2 * tid],
                                          0.5f * an_b2[2 * tid + 1]);
    }
    for (int idx = tid; idx < 4096; idx += NTHREADS)
        sm->Hh[idx >> 6][idx & 63] = __float2half(sm->H[idx >> 6][idx & 63]);
    for (int idx = tid; idx < 8192; idx += NTHREADS) {
        int k = idx >> 7, n = idx & 127;
        W1aT[n * 72 + k] = __float2half(rc_w1[k * 128 + n]);
        W1bT[n * 72 + k] = __float2half(rc_w1[(64 + k) * 128 + n]);
    }
    for (int idx = tid; idx < 4096; idx += NTHREADS) {
        int k = idx >> 6, n = idx & 63;
        AW1aT[n * 72 + k] = __float2half(an_w1[k * 64 + n]);
        AW1bT[n * 72 + k] = __float2half(an_w1[(64 + k) * 64 + n]);
    }
    __syncthreads();

    // ---------------- Phase B: P/Q tables via mma ----------------
    {
        const unsigned HhBase = (unsigned)__cvta_generic_to_shared(&sm->Hh[0][0]);
        const int r0 = 16 * (warp & 3);
        const unsigned addrA = HhBase + (r0 + lrow) * 144 + lcol8 * 2;
        unsigned a[4][4];
        #pragma unroll
        for (int kk = 0; kk < 4; kk++)
            ldm_x4(a[kk][0], a[kk][1], a[kk][2], a[kk][3], addrA + kk * 32);

        if (warp < 8) {
            const bool isP1 = (warp < 4);
            const __half* WT = isP1 ? W1aT : W1bT;
            const unsigned wb = (unsigned)__cvta_generic_to_shared(WT)
                                + trow * 144 + tileid * 16;
            __half* dstT = isP1 ? &sm->P1h[0][0] : &sm->P2h[0][0];
            #pragma unroll
            for (int nt = 0; nt < 16; nt++) {
                float d4[4] = {0.f, 0.f, 0.f, 0.f};
                #pragma unroll
                for (int kk2 = 0; kk2 < 2; kk2++) {
                    unsigned b0, b1, b2, b3;
                    ldm_x4(b0, b1, b2, b3, wb + nt * 1152 + kk2 * 64);
                    mma16816f(d4, a[2 * kk2],     b0, b1);
                    mma16816f(d4, a[2 * kk2 + 1], b2, b3);
                }
                const int c = nt * 8 + t4 * 2;
                float bb0 = isP1 ? rc_b1[c] : 0.f;
                float bb1 = isP1 ? rc_b1[c + 1] : 0.f;
                *reinterpret_cast<__half2*>(dstT + (r0 + g) * 136 + c) =
                    __floats2half2_rn(d4[0] + bb0, d4[1] + bb1);
                *reinterpret_cast<__half2*>(dstT + (r0 + g + 8) * 136 + c) =
                    __floats2half2_rn(d4[2] + bb0, d4[3] + bb1);
            }
        } else if (warp < 12) {
            const unsigned wbA = (unsigned)__cvta_generic_to_shared(AW1aT)
                                 + trow * 144 + tileid * 16;
            const unsigned wbB = (unsigned)__cvta_generic_to_shared(AW1bT)
                                 + trow * 144 + tileid * 16;
            #pragma unroll
            for (int nt = 0; nt < 8; nt++) {
                const int c = nt * 8 + t4 * 2;
                {
                    float d4[4] = {0.f, 0.f, 0.f, 0.f};
                    #pragma unroll
                    for (int kk2 = 0; kk2 < 2; kk2++) {
                        unsigned b0, b1, b2, b3;
                        ldm_x4(b0, b1, b2, b3, wbA + nt * 1152 + kk2 * 64);
                        mma16816f(d4, a[2 * kk2],     b0, b1);
                        mma16816f(d4, a[2 * kk2 + 1], b2, b3);
                    }
                    float bb0 = an_b1[c], bb1 = an_b1[c + 1];
                    *reinterpret_cast<__half2*>(&sm->Q1h[r0 + g][c]) =
                        __floats2half2_rn(d4[0] + bb0, d4[1] + bb1);
                    *reinterpret_cast<__half2*>(&sm->Q1h[r0 + g + 8][c]) =
                        __floats2half2_rn(d4[2] + bb0, d4[3] + bb1);
                }
                {
                    float d4[4] = {0.f, 0.f, 0.f, 0.f};
                    #pragma unroll
                    for (int kk2 = 0; kk2 < 2; kk2++) {
                        unsigned b0, b1, b2, b3;
                        ldm_x4(b0, b1, b2, b3, wbB + nt * 1152 + kk2 * 64);
                        mma16816f(d4, a[2 * kk2],     b0, b1);
                        mma16816f(d4, a[2 * kk2 + 1], b2, b3);
                    }
                    *reinterpret_cast<__half2*>(&sm->Q2h[r0 + g][c]) =
                        __floats2half2_rn(d4[0], d4[1]);
                    *reinterpret_cast<__half2*>(&sm->Q2h[r0 + g + 8][c]) =
                        __floats2half2_rn(d4[2], d4[3]);
                }
            }
        }
    }
    __syncthreads();

    // ---------------- Stage main-loop weights (overwrites overlay) --------
    for (int idx = tid; idx < 16384; idx += NTHREADS) {
        int k = idx >> 7, n = idx & 127;
        sm->W2T[n][k] = __float2half(rc_w2[idx]);
        sm->W3T[n][k] = __float2half(rc_w3[idx]);
    }
    for (int idx = tid; idx < 8192; idx += NTHREADS) {
        int k = idx >> 7, n = idx & 127;
        sm->AW2T[n][k] = __float2half(an_w2[idx]);
    }
    __syncthreads();

    // ---------------- Main loop: 32-pair slabs ----------------
    const unsigned baseW2 = (unsigned)__cvta_generic_to_shared(&sm->W2T[0][0])
                            + trow * 272 + tileid * 16;
    const unsigned baseW3 = (unsigned)__cvta_generic_to_shared(&sm->W3T[0][0])
                            + trow * 272 + tileid * 16;
    const unsigned baseAW = (unsigned)__cvta_generic_to_shared(&sm->AW2T[0][0])
                            + trow * 144 + tileid * 16;
    const unsigned baseP2 = (unsigned)__cvta_generic_to_shared(&sm->P2h[0][0])
                            + lrow * 272 + lcol8 * 2;
    const unsigned baseQ2 = (unsigned)__cvta_generic_to_shared(&sm->Q2h[0][0])
                            + lrow * 144 + lcol8 * 2;

    const __half2 z2 = __floats2half2_rn(0.f, 0.f);
    const __half2 h05 = __floats2half2_rn(0.5f, 0.5f);

    unsigned af2lo[8][4], af2hi[8][4];   // GEMM1 accumulators, then x2 frags
    unsigned afQlo[4][4], afQhi[4][4];

    for (int slab = warp; slab < 128; slab += NWARPS) {
        const int i0 = (slab >> 2) << 1;
        const int i1 = i0 + 1;
        const int j0 = (slab & 3) << 4;
        const int jA = j0 + g;
        const int jB = jA + 8;

        const float hxA = sm->hx[jA], hyA = sm->hy[jA];
        const float hxB = sm->hx[jB], hyB = sm->hy[jB];
        const float xi0 = sm->hx[i0], yi0 = sm->hy[i0];
        const float xi1 = sm->hx[i1], yi1 = sm->hy[i1];
        const unsigned dA0 = h2u(__float2half2_rn(
            (xi0 - hxA) * (xi0 - hxA) + (yi0 - hyA) * (yi0 - hyA)));
        const unsigned dB0 = h2u(__float2half2_rn(
            (xi0 - hxB) * (xi0 - hxB) + (yi0 - hyB) * (yi0 - hyB)));
        const unsigned dA1 = h2u(__float2half2_rn(
            (xi1 - hxA) * (xi1 - hxA) + (yi1 - hyA) * (yi1 - hyA)));
        const unsigned dB1 = h2u(__float2half2_rn(
            (xi1 - hxB) * (xi1 - hxB) + (yi1 - hyB) * (yi1 - hyB)));

        const unsigned addrP2 = baseP2 + j0 * 272;
        const unsigned addrQ2 = baseQ2 + j0 * 144;
        const __half* P1a = sm->P1h[i0];
        const __half* P1b = sm->P1h[i1];
        const __half* Q1a = sm->Q1h[i0];
        const __half* Q1b = sm->Q1h[i1];

        // ---- GEMM1, K-split output-stationary ----
        #pragma unroll
        for (int p = 0; p < 8; p++) {
            af2lo[p][0] = af2lo[p][1] = af2lo[p][2] = af2lo[p][3] = 0u;
            af2hi[p][0] = af2hi[p][1] = af2hi[p][2] = af2hi[p][3] = 0u;
        }
        #pragma unroll
        for (int h = 0; h < 2; h++) {
            // X1 fragments for K-half h (kk = 4h .. 4h+3), transient
            unsigned afl[4][4], afh[4][4];
            #pragma unroll
            for (int l = 0; l < 4; l++) {
                const int kk = 4 * h + l;
                const int c = kk * 16 + t4 * 2;
                unsigned w01 = *reinterpret_cast<const unsigned*>(&sm->w1Lh[c]);
                unsigned w89 = *reinterpret_cast<const unsigned*>(&sm->w1Lh[c + 8]);
                unsigned pa01 = *reinterpret_cast<const unsigned*>(&P1a[c]);
                unsigned pa89 = *reinterpret_cast<const unsigned*>(&P1a[c + 8]);
                unsigned pb01 = *reinterpret_cast<const unsigned*>(&P1b[c]);
                unsigned pb89 = *reinterpret_cast<const unsigned*>(&P1b[c + 8]);
                unsigned f0, f1, f2, f3;
                ldm_x4(f0, f1, f2, f3, addrP2 + kk * 32);
                afl[l][0] = frag_fix(f0, dA0, w01, pa01, z2);
                afl[l][1] = frag_fix(f1, dB0, w01, pa01, z2);
                afl[l][2] = frag_fix(f2, dA0, w89, pa89, z2);
                afl[l][3] = frag_fix(f3, dB0, w89, pa89, z2);
                afh[l][0] = frag_fix(f0, dA1, w01, pb01, z2);
                afh[l][1] = frag_fix(f1, dB1, w01, pb01, z2);
                afh[l][2] = frag_fix(f2, dA1, w89, pb89, z2);
                afh[l][3] = frag_fix(f3, dB1, w89, pb89, z2);
            }
            // sweep all 16 column-subtiles with this K-half
            #pragma unroll
            for (int s2 = 0; s2 < 16; s2++) {
                unsigned* dlo = &af2lo[s2 >> 1][(s2 & 1) * 2];
                unsigned* dhi = &af2hi[s2 >> 1][(s2 & 1) * 2];
                #pragma unroll
                for (int q = 0; q < 2; q++) {
                    const int kk2 = 2 * h + q;
                    unsigned a0, a1, a2, a3;
                    ldm_x4(a0, a1, a2, a3, baseW2 + s2 * 2176 + kk2 * 64);
                    mma16816h(dlo, afl[2 * q],     a0, a1);
                    mma16816h(dlo, afl[2 * q + 1], a2, a3);
                    mma16816h(dhi, afh[2 * q],     a0, a1);
                    mma16816h(dhi, afh[2 * q + 1], a2, a3);
                }
            }
        }
        // in-place bias + relu -> x2 fragments
        #pragma unroll
        for (int p = 0; p < 8; p++) {
            const __half2 b2a = sm->b2h2[p * 8 + t4];
            const __half2 b2b = sm->b2h2[p * 8 + 4 + t4];
            af2lo[p][0] = relu_bias(af2lo[p][0], b2a, z2);
            af2lo[p][1] = relu_bias(af2lo[p][1], b2a, z2);
            af2lo[p][2] = relu_bias(af2lo[p][2], b2b, z2);
            af2lo[p][3] = relu_bias(af2lo[p][3], b2b, z2);
            af2hi[p][0] = relu_bias(af2hi[p][0], b2a, z2);
            af2hi[p][1] = relu_bias(af2hi[p][1], b2a, z2);
            af2hi[p][2] = relu_bias(af2hi[p][2], b2b, z2);
            af2hi[p][3] = relu_bias(af2hi[p][3], b2b, z2);
        }

        // ---- att layer-1 fragments (shared Q2 loads) ----
        #pragma unroll
        for (int kk = 0; kk < 4; kk++) {
            const int c = kk * 16 + t4 * 2;
            unsigned w01 = *reinterpret_cast<const unsigned*>(&sm->aw1Lh[c]);
            unsigned w89 = *reinterpret_cast<const unsigned*>(&sm->aw1Lh[c + 8]);
            unsigned qa01 = *reinterpret_cast<const unsigned*>(&Q1a[c]);
            unsigned qa89 = *reinterpret_cast<const unsigned*>(&Q1a[c + 8]);
            unsigned qb01 = *reinterpret_cast<const unsigned*>(&Q1b[c]);
            unsigned qb89 = *reinterpret_cast<const unsigned*>(&Q1b[c + 8]);
            unsigned f0, f1, f2, f3;
            ldm_x4(f0, f1, f2, f3, addrQ2 + kk * 32);
            afQlo[kk][0] = frag_fix(f0, dA0, w01, qa01, z2);
            afQlo[kk][1] = frag_fix(f1, dB0, w01, qa01, z2);
            afQlo[kk][2] = frag_fix(f2, dA0, w89, qa89, z2);
            afQlo[kk][3] = frag_fix(f3, dB0, w89, qa89, z2);
            afQhi[kk][0] = frag_fix(f0, dA1, w01, qb01, z2);
            afQhi[kk][1] = frag_fix(f1, dB1, w01, qb01, z2);
            afQhi[kk][2] = frag_fix(f2, dA1, w89, qb89, z2);
            afQhi[kk][3] = frag_fix(f3, dB1, w89, qb89, z2);
        }

        // ---- fused GEMM2 + att + half2 sigmoid/combine ----
        #pragma unroll
        for (int nt = 0; nt < 16; nt++) {
            unsigned drlo[2] = {0u, 0u}, drhi[2] = {0u, 0u};
            #pragma unroll
            for (int kk2 = 0; kk2 < 4; kk2++) {
                unsigned r0, r1, r2, r3;
                ldm_x4(r0, r1, r2, r3, baseW3 + nt * 2176 + kk2 * 64);
                mma16816h(drlo, af2lo[2 * kk2],     r0, r1);
                mma16816h(drlo, af2lo[2 * kk2 + 1], r2, r3);
                mma16816h(drhi, af2hi[2 * kk2],     r0, r1);
                mma16816h(drhi, af2hi[2 * kk2 + 1], r2, r3);
            }
            unsigned dalo[2] = {0u, 0u}, dahi[2] = {0u, 0u};
            #pragma unroll
            for (int kk2 = 0; kk2 < 2; kk2++) {
                unsigned r0, r1, r2, r3;
                ldm_x4(r0, r1, r2, r3, baseAW + nt * 1152 + kk2 * 64);
                mma16816h(dalo, afQlo[2 * kk2],     r0, r1);
                mma16816h(dalo, afQlo[2 * kk2 + 1], r2, r3);
                mma16816h(dahi, afQhi[2 * kk2],     r0, r1);
                mma16816h(dahi, afQhi[2 * kk2 + 1], r2, r3);
            }
            const int c0 = nt * 8 + t4 * 2;
            const __half2 b3p = sm->b3h2[nt * 4 + t4];
            const __half2 abp = sm->abh2[nt * 4 + t4];
            __half2 sA = sigmoid_h2(dalo[0], abp, h05);
            __half2 sB = sigmoid_h2(dalo[1], abp, h05);
            __half2 sC = sigmoid_h2(dahi[0], abp, h05);
            __half2 sD = sigmoid_h2(dahi[1], abp, h05);
            __half2 rA = __hmax2(__hadd2(u2h(drlo[0]), b3p), z2);
            __half2 rB = __hmax2(__hadd2(u2h(drlo[1]), b3p), z2);
            __half2 rC = __hmax2(__hadd2(u2h(drhi[0]), b3p), z2);
            __half2 rD = __hmax2(__hadd2(u2h(drhi[1]), b3p), z2);
            __half2 vh = __hmul2(rA, sA);
            vh = __hfma2(rB, sB, vh);
            vh = __hfma2(rC, sC, vh);
            vh = __hfma2(rD, sD, vh);
            float2 vf = __half22float2(vh);
            float v0 = vf.x, v1 = vf.y;
            v0 += __shfl_xor_sync(0xffffffffu, v0, 4);
            v0 += __shfl_xor_sync(0xffffffffu, v0, 8);
            v0 += __shfl_xor_sync(0xffffffffu, v0, 16);
            v1 += __shfl_xor_sync(0xffffffffu, v1, 4);
            v1 += __shfl_xor_sync(0xffffffffu, v1, 8);
            v1 += __shfl_xor_sync(0xffffffffu, v1, 16);
            if (lane < 4) {
                atomicAdd(&sm->accs[c0], v0);
                atomicAdd(&sm->accs[c0 + 1], v1);
            }
        }
    }
    __syncthreads();

    // ---------------- Epilogue: self_dyn layer-1 via mma ----------------
    {
        __half* SW1T = reinterpret_cast<__half*>(ovl);  // [128][72] over W2T
        for (int idx = tid; idx < 8192; idx += NTHREADS) {
            int k = idx >> 7, n = idx & 127;
            SW1T[n * 72 + k] = __float2half(sd_w1[k * 128 + n]);
        }
        __syncthreads();
        if (warp < 4) {
            const unsigned HhBase =
                (unsigned)__cvta_generic_to_shared(&sm->Hh[0][0]);
            const int r0 = 16 * warp;
            const unsigned addrA = HhBase + (r0 + lrow) * 144 + lcol8 * 2;
            unsigned a[4][4];
            #pragma unroll
            for (int kk = 0; kk < 4; kk++)
                ldm_x4(a[kk][0], a[kk][1], a[kk][2], a[kk][3], addrA + kk * 32);
            const unsigned wb = (unsigned)__cvta_generic_to_shared(SW1T)
                                + trow * 144 + tileid * 16;
            #pragma unroll
            for (int nt = 0; nt < 16; nt++) {
                float d4[4] = {0.f, 0.f, 0.f, 0.f};
                #pragma unroll
                for (int kk2 = 0; kk2 < 2; kk2++) {
                    unsigned b0, b1, b2, b3;
                    ldm_x4(b0, b1, b2, b3, wb + nt * 1152 + kk2 * 64);
                    mma16816f(d4, a[2 * kk2],     b0, b1);
                    mma16816f(d4, a[2 * kk2 + 1], b2, b3);
                }
                const int c = nt * 8 + t4 * 2;
                float bb0 = sd_b1[c], bb1 = sd_b1[c + 1];
                float v0 = fmaxf(d4[0] + bb0, 0.f) + fmaxf(d4[2] + bb0, 0.f);
                float v1 = fmaxf(d4[1] + bb1, 0.f) + fmaxf(d4[3] + bb1, 0.f);
                v0 += __shfl_xor_sync(0xffffffffu, v0, 4);
                v0 += __shfl_xor_sync(0xffffffffu, v0, 8);
                v0 += __shfl_xor_sync(0xffffffffu, v0, 16);
                v1 += __shfl_xor_sync(0xffffffffu, v1, 4);
                v1 += __shfl_xor_sync(0xffffffffu, v1, 8);
                v1 += __shfl_xor_sync(0xffffffffu, v1, 16);
                if (lane < 4) {
                    atomicAdd(&sm->msum[c], v0);
                    atomicAdd(&sm->msum[c + 1], v1);
                }
            }
        }
    }
    __syncthreads();
    if (tid < 128) {
        // contraction over 2cl = 128 dims (sd_w2 is 128x128)
        float r = sd_b2[tid] + sm->accs[tid] * (1.f / 4096.f);
        #pragma unroll 8
        for (int k = 0; k < 128; k++)
            r += (sm->msum[k] * (1.f / 64.f)) * sd_w2[k * 128 + tid];
        out[(size_t)b * 128 + tid] = r;
    }
}

extern "C" void kernel_launch(void* const* d_in, const int* in_sizes, int n_in,
                              void* d_out, int out_size) {
    (void)in_sizes; (void)n_in; (void)out_size;
    cudaFuncSetAttribute(sgh_kernel, cudaFuncAttributeMaxDynamicSharedMemorySize,
                         (int)sizeof(Smem));
    const float* s     = (const float*)d_in[0];
    const float* se_w1 = (const float*)d_in[1];
    const float* se_b1 = (const float*)d_in[2];
    const float* se_w2 = (const float*)d_in[3];
    const float* se_b2 = (const float*)d_in[4];
    const float* sd_w1 = (const float*)d_in[5];
    const float* sd_b1 = (const float*)d_in[6];
    const float* sd_w2 = (const float*)d_in[7];
    const float* sd_b2 = (const float*)d_in[8];
    const float* rc_w1 = (const float*)d_in[9];
    const float* rc_b1 = (const float*)d_in[10];
    const float* rc_w2 = (const float*)d_in[11];
    const float* rc_b2 = (const float*)d_in[12];
    const float* rc_w3 = (const float*)d_in[13];
    const float* rc_b3 = (const float*)d_in[14];
    const float* an_w1 = (const float*)d_in[15];
    const float* an_b1 = (const float*)d_in[16];
    const float* an_w2 = (const float*)d_in[17];
    const float* an_b2 = (const float*)d_in[18];

    sgh_kernel<<<128, NTHREADS, sizeof(Smem)>>>(
        s, se_w1, se_b1, se_w2, se_b2, sd_w1, sd_b1, sd_w2, sd_b2,
        rc_w1, rc_b1, rc_w2, rc_b2, rc_w3, rc_b3,
        an_w1, an_b1, an_w2, an_b2, (float*)d_out);
}

// round 12
// speedup vs baseline: 1.3183x; 1.3183x over previous
#include <cuda_runtime.h>
#include <cuda_fp16.h>

// SimpleGraphHead fused kernel, round 12.
// B=128, N=64, cl=64. One CTA per batch, 12 warps (168 regs, no spills).
// NEW vs r9 baseline: Phase A (state encoder) via mma in-place in Hh;
// persistent vacc accumulators (one flush per warp); half2-vectorized
// transposed weight staging. Main loop structure unchanged.

#define NWARPS 12
#define NTHREADS 384

struct Smem {
    __half Hh[64][72];       // fp16 H (also Phase-A working buffer), row=144B
    __half P1h[64][136];     // row=272B
    __half P2h[64][136];
    __half Q1h[64][72];      // row=144B
    __half Q2h[64][72];
    __half W2T[128][136];    // overlay region starts here (88 KB)
    __half W3T[128][136];
    __half AW2T[128][72];
    __half w1Lh[128];
    __half aw1Lh[64];
    __half2 b2h2[64];
    __half2 b3h2[64];
    __half2 abh2[64];        // 0.5*an_b2 pairs
    float  hx[64], hy[64];
    float  accs[128];
    float  msum[128];
};

__device__ __forceinline__ __half2 u2h(unsigned u) {
    return *reinterpret_cast<__half2*>(&u);
}
__device__ __forceinline__ unsigned h2u(__half2 h) {
    return *reinterpret_cast<unsigned*>(&h);
}
__device__ __forceinline__ unsigned tanh_h2(unsigned x) {
    unsigned y;
    asm("tanh.approx.f16x2 %0, %1;" : "=r"(y) : "r"(x));
    return y;
}
// f16-accumulate mma
__device__ __forceinline__ void mma16816h(unsigned* d, const unsigned* a,
                                          unsigned b0, unsigned b1) {
    asm volatile(
        "mma.sync.aligned.m16n8k16.row.col.f16.f16.f16.f16 "
        "{%0,%1}, {%2,%3,%4,%5}, {%6,%7}, {%0,%1};\n"
        : "+r"(d[0]), "+r"(d[1])
        : "r"(a[0]), "r"(a[1]), "r"(a[2]), "r"(a[3]), "r"(b0), "r"(b1));
}
// f32-accumulate mma (for table builds)
__device__ __forceinline__ void mma16816f(float* d, const unsigned* a,
                                          unsigned b0, unsigned b1) {
    asm volatile(
        "mma.sync.aligned.m16n8k16.row.col.f32.f16.f16.f32 "
        "{%0,%1,%2,%3}, {%4,%5,%6,%7}, {%8,%9}, {%0,%1,%2,%3};\n"
        : "+f"(d[0]), "+f"(d[1]), "+f"(d[2]), "+f"(d[3])
        : "r"(a[0]), "r"(a[1]), "r"(a[2]), "r"(a[3]), "r"(b0), "r"(b1));
}
__device__ __forceinline__ void ldm_x4(unsigned& r0, unsigned& r1,
                                       unsigned& r2, unsigned& r3,
                                       unsigned saddr) {
    asm volatile("ldmatrix.sync.aligned.m8n8.x4.shared.b16 {%0,%1,%2,%3}, [%4];"
                 : "=r"(r0), "=r"(r1), "=r"(r2), "=r"(r3) : "r"(saddr));
}
__device__ __forceinline__ unsigned frag_fix(unsigned p2f, unsigned d2,
                                             unsigned w, unsigned base,
                                             __half2 z2) {
    __half2 corr = __hfma2(u2h(d2), u2h(w), u2h(base));
    return h2u(__hmax2(__hadd2(u2h(p2f), corr), z2));
}
__device__ __forceinline__ unsigned relu_bias(unsigned acc, __half2 bias,
                                              __half2 z2) {
    return h2u(__hmax2(__hadd2(u2h(acc), bias), z2));
}
// sigmoid(da + ab) = 0.5*tanh(0.5*da + 0.5*ab) + 0.5, all half2
__device__ __forceinline__ __half2 sigmoid_h2(unsigned da, __half2 abp,
                                              __half2 h05) {
    unsigned t = h2u(__hfma2(u2h(da), h05, abp));
    return __hfma2(u2h(tanh_h2(t)), h05, h05);
}

__global__ void __launch_bounds__(NTHREADS, 1)
sgh_kernel(const float* __restrict__ s,
           const float* __restrict__ se_w1, const float* __restrict__ se_b1,
           const float* __restrict__ se_w2, const float* __restrict__ se_b2,
           const float* __restrict__ sd_w1, const float* __restrict__ sd_b1,
           const float* __restrict__ sd_w2, const float* __restrict__ sd_b2,
           const float* __restrict__ rc_w1, const float* __restrict__ rc_b1,
           const float* __restrict__ rc_w2, const float* __restrict__ rc_b2,
           const float* __restrict__ rc_w3, const float* __restrict__ rc_b3,
           const float* __restrict__ an_w1, const float* __restrict__ an_b1,
           const float* __restrict__ an_w2, const float* __restrict__ an_b2,
           float* __restrict__ out) {
    extern __shared__ char smraw[];
    Smem* sm = reinterpret_cast<Smem*>(smraw);
    const int b = blockIdx.x;
    const int tid = threadIdx.x;
    const int warp = tid >> 5;
    const int lane = tid & 31;
    const int g  = lane >> 2;
    const int t4 = lane & 3;
    const int trow = lane & 7;
    const int tileid = lane >> 3;
    const int lrow  = lane & 15;
    const int lcol8 = (lane >> 4) << 3;

    // Overlay region (88 KB spanning W2T/W3T/AW2T)
    char* ovl = reinterpret_cast<char*>(&sm->W2T[0][0]);
    __half* SE1T  = reinterpret_cast<__half*>(ovl);          // [64][72]
    __half* SE2T  = reinterpret_cast<__half*>(ovl + 9216);   // [64][72]
    __half* W1aT  = reinterpret_cast<__half*>(ovl + 18432);  // [128][72]
    __half* W1bT  = reinterpret_cast<__half*>(ovl + 36864);  // [128][72]
    __half* AW1aT = reinterpret_cast<__half*>(ovl + 55296);  // [64][72]
    __half* AW1bT = reinterpret_cast<__half*>(ovl + 64512);  // [64][72]

    // ---------------- Stage everything for Phase A + B ----------------
    const float* sb = s + (size_t)b * 64 * 64;
    // s -> fp16 into Hh (Phase-A working buffer)
    for (int idx = tid; idx < 4096; idx += NTHREADS)
        sm->Hh[idx >> 6][idx & 63] = __float2half(sb[idx]);
    // SE1T/SE2T: transposed fp16 encoder weights (half2 stores)
    for (int idx = tid; idx < 2048; idx += NTHREADS) {
        int k = (idx >> 6) << 1, n = idx & 63;
        *reinterpret_cast<__half2*>(&SE1T[n * 72 + k]) =
            __floats2half2_rn(se_w1[k * 64 + n], se_w1[(k + 1) * 64 + n]);
        *reinterpret_cast<__half2*>(&SE2T[n * 72 + k]) =
            __floats2half2_rn(se_w2[k * 64 + n], se_w2[(k + 1) * 64 + n]);
    }
    // W1aT/W1bT: rc_w1 halves, transposed
    for (int idx = tid; idx < 4096; idx += NTHREADS) {
        int k = (idx >> 7) << 1, n = idx & 127;
        *reinterpret_cast<__half2*>(&W1aT[n * 72 + k]) =
            __floats2half2_rn(rc_w1[k * 128 + n], rc_w1[(k + 1) * 128 + n]);
        *reinterpret_cast<__half2*>(&W1bT[n * 72 + k]) =
            __floats2half2_rn(rc_w1[(64 + k) * 128 + n],
                              rc_w1[(65 + k) * 128 + n]);
    }
    // AW1aT/AW1bT: an_w1 halves, transposed
    for (int idx = tid; idx < 2048; idx += NTHREADS) {
        int k = (idx >> 6) << 1, n = idx & 63;
        *reinterpret_cast<__half2*>(&AW1aT[n * 72 + k]) =
            __floats2half2_rn(an_w1[k * 64 + n], an_w1[(k + 1) * 64 + n]);
        *reinterpret_cast<__half2*>(&AW1bT[n * 72 + k]) =
            __floats2half2_rn(an_w1[(64 + k) * 64 + n],
                              an_w1[(65 + k) * 64 + n]);
    }
    if (tid < 128) {
        sm->w1Lh[tid] = __float2half(rc_w1[128 * 128 + tid]);
        sm->accs[tid] = 0.f;
        sm->msum[tid] = 0.f;
    }
    if (tid < 64) {
        sm->aw1Lh[tid] = __float2half(an_w1[128 * 64 + tid]);
        sm->b2h2[tid] = __floats2half2_rn(rc_b2[2 * tid], rc_b2[2 * tid + 1]);
        sm->b3h2[tid] = __floats2half2_rn(rc_b3[2 * tid], rc_b3[2 * tid + 1]);
        sm->abh2[tid] = __floats2half2_rn(0.5f * an_b2[2 * tid],
                                          0.5f * an_b2[2 * tid + 1]);
    }
    __syncthreads();

    // ---------------- Phase A: state encoder via mma, in-place in Hh ------
    {
        const unsigned ThBase =
            (unsigned)__cvta_generic_to_shared(&sm->Hh[0][0]);
        const int r0 = 16 * (warp & 3);
        const int half = warp >> 2;   // warps 0-7 active (half 0/1)
        const unsigned addrA = ThBase + (r0 + lrow) * 144 + lcol8 * 2;

        #pragma unroll 1
        for (int layer = 0; layer < 2; layer++) {
            const __half* WT = layer ? SE2T : SE1T;
            const float* bias = layer ? se_b2 : se_b1;
            unsigned a[4][4];
            if (warp < 8) {
                #pragma unroll
                for (int kk = 0; kk < 4; kk++)
                    ldm_x4(a[kk][0], a[kk][1], a[kk][2], a[kk][3],
                           addrA + kk * 32);
            }
            __syncthreads();   // all reads of Th done before any store
            if (warp < 8) {
                const unsigned wb = (unsigned)__cvta_generic_to_shared(WT)
                                    + trow * 144 + tileid * 16;
                #pragma unroll
                for (int t = 0; t < 4; t++) {
                    const int nt = half * 4 + t;
                    float d4[4] = {0.f, 0.f, 0.f, 0.f};
                    #pragma unroll
                    for (int kk2 = 0; kk2 < 2; kk2++) {
                        unsigned b0, b1, b2, b3;
                        ldm_x4(b0, b1, b2, b3, wb + nt * 1152 + kk2 * 64);
                        mma16816f(d4, a[2 * kk2],     b0, b1);
                        mma16816f(d4, a[2 * kk2 + 1], b2, b3);
                    }
                    const int c = nt * 8 + t4 * 2;
                    float bb0 = bias[c], bb1 = bias[c + 1];
                    float h0 = fmaxf(d4[0] + bb0, 0.f);
                    float h1 = fmaxf(d4[1] + bb1, 0.f);
                    float h2 = fmaxf(d4[2] + bb0, 0.f);
                    float h3 = fmaxf(d4[3] + bb1, 0.f);
                    *reinterpret_cast<__half2*>(&sm->Hh[r0 + g][c]) =
                        __floats2half2_rn(h0, h1);
                    *reinterpret_cast<__half2*>(&sm->Hh[r0 + g + 8][c]) =
                        __floats2half2_rn(h2, h3);
                    if (layer == 1 && nt == 0 && t4 == 0) {
                        sm->hx[r0 + g] = h0;     sm->hy[r0 + g] = h1;
                        sm->hx[r0 + g + 8] = h2; sm->hy[r0 + g + 8] = h3;
                    }
                }
            }
            __syncthreads();   // stores visible before next layer's reads
        }
    }

    // ---------------- Phase B: P/Q tables via mma ----------------
    {
        const unsigned HhBase = (unsigned)__cvta_generic_to_shared(&sm->Hh[0][0]);
        const int r0 = 16 * (warp & 3);
        const unsigned addrA = HhBase + (r0 + lrow) * 144 + lcol8 * 2;
        unsigned a[4][4];
        #pragma unroll
        for (int kk = 0; kk < 4; kk++)
            ldm_x4(a[kk][0], a[kk][1], a[kk][2], a[kk][3], addrA + kk * 32);

        if (warp < 8) {
            const bool isP1 = (warp < 4);
            const __half* WT = isP1 ? W1aT : W1bT;
            const unsigned wb = (unsigned)__cvta_generic_to_shared(WT)
                                + trow * 144 + tileid * 16;
            __half* dstT = isP1 ? &sm->P1h[0][0] : &sm->P2h[0][0];
            #pragma unroll
            for (int nt = 0; nt < 16; nt++) {
                float d4[4] = {0.f, 0.f, 0.f, 0.f};
                #pragma unroll
                for (int kk2 = 0; kk2 < 2; kk2++) {
                    unsigned b0, b1, b2, b3;
                    ldm_x4(b0, b1, b2, b3, wb + nt * 1152 + kk2 * 64);
                    mma16816f(d4, a[2 * kk2],     b0, b1);
                    mma16816f(d4, a[2 * kk2 + 1], b2, b3);
                }
                const int c = nt * 8 + t4 * 2;
                float bb0 = isP1 ? rc_b1[c] : 0.f;
                float bb1 = isP1 ? rc_b1[c + 1] : 0.f;
                *reinterpret_cast<__half2*>(dstT + (r0 + g) * 136 + c) =
                    __floats2half2_rn(d4[0] + bb0, d4[1] + bb1);
                *reinterpret_cast<__half2*>(dstT + (r0 + g + 8) * 136 + c) =
                    __floats2half2_rn(d4[2] + bb0, d4[3] + bb1);
            }
        } else {
            const unsigned wbA = (unsigned)__cvta_generic_to_shared(AW1aT)
                                 + trow * 144 + tileid * 16;
            const unsigned wbB = (unsigned)__cvta_generic_to_shared(AW1bT)
                                 + trow * 144 + tileid * 16;
            #pragma unroll
            for (int nt = 0; nt < 8; nt++) {
                const int c = nt * 8 + t4 * 2;
                {
                    float d4[4] = {0.f, 0.f, 0.f, 0.f};
                    #pragma unroll
                    for (int kk2 = 0; kk2 < 2; kk2++) {
                        unsigned b0, b1, b2, b3;
                        ldm_x4(b0, b1, b2, b3, wbA + nt * 1152 + kk2 * 64);
                        mma16816f(d4, a[2 * kk2],     b0, b1);
                        mma16816f(d4, a[2 * kk2 + 1], b2, b3);
                    }
                    float bb0 = an_b1[c], bb1 = an_b1[c + 1];
                    *reinterpret_cast<__half2*>(&sm->Q1h[r0 + g][c]) =
                        __floats2half2_rn(d4[0] + bb0, d4[1] + bb1);
                    *reinterpret_cast<__half2*>(&sm->Q1h[r0 + g + 8][c]) =
                        __floats2half2_rn(d4[2] + bb0, d4[3] + bb1);
                }
                {
                    float d4[4] = {0.f, 0.f, 0.f, 0.f};
                    #pragma unroll
                    for (int kk2 = 0; kk2 < 2; kk2++) {
                        unsigned b0, b1, b2, b3;
                        ldm_x4(b0, b1, b2, b3, wbB + nt * 1152 + kk2 * 64);
                        mma16816f(d4, a[2 * kk2],     b0, b1);
                        mma16816f(d4, a[2 * kk2 + 1], b2, b3);
                    }
                    *reinterpret_cast<__half2*>(&sm->Q2h[r0 + g][c]) =
                        __floats2half2_rn(d4[0], d4[1]);
                    *reinterpret_cast<__half2*>(&sm->Q2h[r0 + g + 8][c]) =
                        __floats2half2_rn(d4[2], d4[3]);
                }
            }
        }
    }
    __syncthreads();

    // ---------------- Stage main-loop weights (overwrites overlay) --------
    for (int idx = tid; idx < 8192; idx += NTHREADS) {
        int k = (idx >> 7) << 1, n = idx & 127;
        *reinterpret_cast<__half2*>(&sm->W2T[n][k]) =
            __floats2half2_rn(rc_w2[k * 128 + n], rc_w2[(k + 1) * 128 + n]);
        *reinterpret_cast<__half2*>(&sm->W3T[n][k]) =
            __floats2half2_rn(rc_w3[k * 128 + n], rc_w3[(k + 1) * 128 + n]);
    }
    for (int idx = tid; idx < 4096; idx += NTHREADS) {
        int k = (idx >> 7) << 1, n = idx & 127;
        *reinterpret_cast<__half2*>(&sm->AW2T[n][k]) =
            __floats2half2_rn(an_w2[k * 128 + n], an_w2[(k + 1) * 128 + n]);
    }
    __syncthreads();

    // ---------------- Main loop: 32-pair slabs ----------------
    const unsigned baseW2 = (unsigned)__cvta_generic_to_shared(&sm->W2T[0][0])
                            + trow * 272 + tileid * 16;
    const unsigned baseW3 = (unsigned)__cvta_generic_to_shared(&sm->W3T[0][0])
                            + trow * 272 + tileid * 16;
    const unsigned baseAW = (unsigned)__cvta_generic_to_shared(&sm->AW2T[0][0])
                            + trow * 144 + tileid * 16;
    const unsigned baseP2 = (unsigned)__cvta_generic_to_shared(&sm->P2h[0][0])
                            + lrow * 272 + lcol8 * 2;
    const unsigned baseQ2 = (unsigned)__cvta_generic_to_shared(&sm->Q2h[0][0])
                            + lrow * 144 + lcol8 * 2;

    const __half2 z2 = __floats2half2_rn(0.f, 0.f);
    const __half2 h05 = __floats2half2_rn(0.5f, 0.5f);

    unsigned af2lo[8][4], af2hi[8][4];   // GEMM1 accumulators, then x2 frags
    unsigned afQlo[4][4], afQhi[4][4];
    float vacc0[16], vacc1[16];
    #pragma unroll
    for (int nt = 0; nt < 16; nt++) { vacc0[nt] = 0.f; vacc1[nt] = 0.f; }

    for (int slab = warp; slab < 128; slab += NWARPS) {
        const int i0 = (slab >> 2) << 1;
        const int i1 = i0 + 1;
        const int j0 = (slab & 3) << 4;
        const int jA = j0 + g;
        const int jB = jA + 8;

        const float hxA = sm->hx[jA], hyA = sm->hy[jA];
        const float hxB = sm->hx[jB], hyB = sm->hy[jB];
        const float xi0 = sm->hx[i0], yi0 = sm->hy[i0];
        const float xi1 = sm->hx[i1], yi1 = sm->hy[i1];
        const unsigned dA0 = h2u(__float2half2_rn(
            (xi0 - hxA) * (xi0 - hxA) + (yi0 - hyA) * (yi0 - hyA)));
        const unsigned dB0 = h2u(__float2half2_rn(
            (xi0 - hxB) * (xi0 - hxB) + (yi0 - hyB) * (yi0 - hyB)));
        const unsigned dA1 = h2u(__float2half2_rn(
            (xi1 - hxA) * (xi1 - hxA) + (yi1 - hyA) * (yi1 - hyA)));
        const unsigned dB1 = h2u(__float2half2_rn(
            (xi1 - hxB) * (xi1 - hxB) + (yi1 - hyB) * (yi1 - hyB)));

        const unsigned addrP2 = baseP2 + j0 * 272;
        const unsigned addrQ2 = baseQ2 + j0 * 144;
        const __half* P1a = sm->P1h[i0];
        const __half* P1b = sm->P1h[i1];
        const __half* Q1a = sm->Q1h[i0];
        const __half* Q1b = sm->Q1h[i1];

        // ---- GEMM1, K-split output-stationary ----
        #pragma unroll
        for (int p = 0; p < 8; p++) {
            af2lo[p][0] = af2lo[p][1] = af2lo[p][2] = af2lo[p][3] = 0u;
            af2hi[p][0] = af2hi[p][1] = af2hi[p][2] = af2hi[p][3] = 0u;
        }
        #pragma unroll
        for (int h = 0; h < 2; h++) {
            unsigned afl[4][4], afh[4][4];
            #pragma unroll
            for (int l = 0; l < 4; l++) {
                const int kk = 4 * h + l;
                const int c = kk * 16 + t4 * 2;
                unsigned w01 = *reinterpret_cast<const unsigned*>(&sm->w1Lh[c]);
                unsigned w89 = *reinterpret_cast<const unsigned*>(&sm->w1Lh[c + 8]);
                unsigned pa01 = *reinterpret_cast<const unsigned*>(&P1a[c]);
                unsigned pa89 = *reinterpret_cast<const unsigned*>(&P1a[c + 8]);
                unsigned pb01 = *reinterpret_cast<const unsigned*>(&P1b[c]);
                unsigned pb89 = *reinterpret_cast<const unsigned*>(&P1b[c + 8]);
                unsigned f0, f1, f2, f3;
                ldm_x4(f0, f1, f2, f3, addrP2 + kk * 32);
                afl[l][0] = frag_fix(f0, dA0, w01, pa01, z2);
                afl[l][1] = frag_fix(f1, dB0, w01, pa01, z2);
                afl[l][2] = frag_fix(f2, dA0, w89, pa89, z2);
                afl[l][3] = frag_fix(f3, dB0, w89, pa89, z2);
                afh[l][0] = frag_fix(f0, dA1, w01, pb01, z2);
                afh[l][1] = frag_fix(f1, dB1, w01, pb01, z2);
                afh[l][2] = frag_fix(f2, dA1, w89, pb89, z2);
                afh[l][3] = frag_fix(f3, dB1, w89, pb89, z2);
            }
            #pragma unroll
            for (int s2 = 0; s2 < 16; s2++) {
                unsigned* dlo = &af2lo[s2 >> 1][(s2 & 1) * 2];
                unsigned* dhi = &af2hi[s2 >> 1][(s2 & 1) * 2];
                #pragma unroll
                for (int q = 0; q < 2; q++) {
                    const int kk2 = 2 * h + q;
                    unsigned a0, a1, a2, a3;
                    ldm_x4(a0, a1, a2, a3, baseW2 + s2 * 2176 + kk2 * 64);
                    mma16816h(dlo, afl[2 * q],     a0, a1);
                    mma16816h(dlo, afl[2 * q + 1], a2, a3);
                    mma16816h(dhi, afh[2 * q],     a0, a1);
                    mma16816h(dhi, afh[2 * q + 1], a2, a3);
                }
            }
        }
        // in-place bias + relu -> x2 fragments
        #pragma unroll
        for (int p = 0; p < 8; p++) {
            const __half2 b2a = sm->b2h2[p * 8 + t4];
            const __half2 b2b = sm->b2h2[p * 8 + 4 + t4];
            af2lo[p][0] = relu_bias(af2lo[p][0], b2a, z2);
            af2lo[p][1] = relu_bias(af2lo[p][1], b2a, z2);
            af2lo[p][2] = relu_bias(af2lo[p][2], b2b, z2);
            af2lo[p][3] = relu_bias(af2lo[p][3], b2b, z2);
            af2hi[p][0] = relu_bias(af2hi[p][0], b2a, z2);
            af2hi[p][1] = relu_bias(af2hi[p][1], b2a, z2);
            af2hi[p][2] = relu_bias(af2hi[p][2], b2b, z2);
            af2hi[p][3] = relu_bias(af2hi[p][3], b2b, z2);
        }

        // ---- att layer-1 fragments (shared Q2 loads) ----
        #pragma unroll
        for (int kk = 0; kk < 4; kk++) {
            const int c = kk * 16 + t4 * 2;
            unsigned w01 = *reinterpret_cast<const unsigned*>(&sm->aw1Lh[c]);
            unsigned w89 = *reinterpret_cast<const unsigned*>(&sm->aw1Lh[c + 8]);
            unsigned qa01 = *reinterpret_cast<const unsigned*>(&Q1a[c]);
            unsigned qa89 = *reinterpret_cast<const unsigned*>(&Q1a[c + 8]);
            unsigned qb01 = *reinterpret_cast<const unsigned*>(&Q1b[c]);
            unsigned qb89 = *reinterpret_cast<const unsigned*>(&Q1b[c + 8]);
            unsigned f0, f1, f2, f3;
            ldm_x4(f0, f1, f2, f3, addrQ2 + kk * 32);
            afQlo[kk][0] = frag_fix(f0, dA0, w01, qa01, z2);
            afQlo[kk][1] = frag_fix(f1, dB0, w01, qa01, z2);
            afQlo[kk][2] = frag_fix(f2, dA0, w89, qa89, z2);
            afQlo[kk][3] = frag_fix(f3, dB0, w89, qa89, z2);
            afQhi[kk][0] = frag_fix(f0, dA1, w01, qb01, z2);
            afQhi[kk][1] = frag_fix(f1, dB1, w01, qb01, z2);
            afQhi[kk][2] = frag_fix(f2, dA1, w89, qb89, z2);
            afQhi[kk][3] = frag_fix(f3, dB1, w89, qb89, z2);
        }

        // ---- fused GEMM2 + att + half2 sigmoid/combine -> vacc ----
        #pragma unroll
        for (int nt = 0; nt < 16; nt++) {
            unsigned drlo[2] = {0u, 0u}, drhi[2] = {0u, 0u};
            #pragma unroll
            for (int kk2 = 0; kk2 < 4; kk2++) {
                unsigned r0, r1, r2, r3;
                ldm_x4(r0, r1, r2, r3, baseW3 + nt * 2176 + kk2 * 64);
                mma16816h(drlo, af2lo[2 * kk2],     r0, r1);
                mma16816h(drlo, af2lo[2 * kk2 + 1], r2, r3);
                mma16816h(drhi, af2hi[2 * kk2],     r0, r1);
                mma16816h(drhi, af2hi[2 * kk2 + 1], r2, r3);
            }
            unsigned dalo[2] = {0u, 0u}, dahi[2] = {0u, 0u};
            #pragma unroll
            for (int kk2 = 0; kk2 < 2; kk2++) {
                unsigned r0, r1, r2, r3;
                ldm_x4(r0, r1, r2, r3, baseAW + nt * 1152 + kk2 * 64);
                mma16816h(dalo, afQlo[2 * kk2],     r0, r1);
                mma16816h(dalo, afQlo[2 * kk2 + 1], r2, r3);
                mma16816h(dahi, afQhi[2 * kk2],     r0, r1);
                mma16816h(dahi, afQhi[2 * kk2 + 1], r2, r3);
            }
            const __half2 b3p = sm->b3h2[nt * 4 + t4];
            const __half2 abp = sm->abh2[nt * 4 + t4];
            __half2 sA = sigmoid_h2(dalo[0], abp, h05);
            __half2 sB = sigmoid_h2(dalo[1], abp, h05);
            __half2 sC = sigmoid_h2(dahi[0], abp, h05);
            __half2 sD = sigmoid_h2(dahi[1], abp, h05);
            __half2 rA = __hmax2(__hadd2(u2h(drlo[0]), b3p), z2);
            __half2 rB = __hmax2(__hadd2(u2h(drlo[1]), b3p), z2);
            __half2 rC = __hmax2(__hadd2(u2h(drhi[0]), b3p), z2);
            __half2 rD = __hmax2(__hadd2(u2h(drhi[1]), b3p), z2);
            __half2 vh = __hmul2(rA, sA);
            vh = __hfma2(rB, sB, vh);
            vh = __hfma2(rC, sC, vh);
            vh = __hfma2(rD, sD, vh);
            float2 vf = __half22float2(vh);
            vacc0[nt] += vf.x;
            vacc1[nt] += vf.y;
        }
    }

    // ---- one reduction per warp ----
    #pragma unroll
    for (int nt = 0; nt < 16; nt++) {
        float v0 = vacc0[nt], v1 = vacc1[nt];
        v0 += __shfl_xor_sync(0xffffffffu, v0, 4);
        v0 += __shfl_xor_sync(0xffffffffu, v0, 8);
        v0 += __shfl_xor_sync(0xffffffffu, v0, 16);
        v1 += __shfl_xor_sync(0xffffffffu, v1, 4);
        v1 += __shfl_xor_sync(0xffffffffu, v1, 8);
        v1 += __shfl_xor_sync(0xffffffffu, v1, 16);
        if (lane < 4) {
            atomicAdd(&sm->accs[nt * 8 + lane * 2], v0);
            atomicAdd(&sm->accs[nt * 8 + lane * 2 + 1], v1);
        }
    }
    __syncthreads();

    // ---------------- Epilogue: self_dyn layer-1 via mma ----------------
    {
        __half* SW1T = reinterpret_cast<__half*>(ovl);  // [128][72] over W2T
        for (int idx = tid; idx < 4096; idx += NTHREADS) {
            int k = (idx >> 7) << 1, n = idx & 127;
            *reinterpret_cast<__half2*>(&SW1T[n * 72 + k]) =
                __floats2half2_rn(sd_w1[k * 128 + n], sd_w1[(k + 1) * 128 + n]);
        }
        __syncthreads();
        if (warp < 4) {
            const unsigned HhBase =
                (unsigned)__cvta_generic_to_shared(&sm->Hh[0][0]);
            const int r0 = 16 * warp;
            const unsigned addrA = HhBase + (r0 + lrow) * 144 + lcol8 * 2;
            unsigned a[4][4];
            #pragma unroll
            for (int kk = 0; kk < 4; kk++)
                ldm_x4(a[kk][0], a[kk][1], a[kk][2], a[kk][3], addrA + kk * 32);
            const unsigned wb = (unsigned)__cvta_generic_to_shared(SW1T)
                                + trow * 144 + tileid * 16;
            #pragma unroll
            for (int nt = 0; nt < 16; nt++) {
                float d4[4] = {0.f, 0.f, 0.f, 0.f};
                #pragma unroll
                for (int kk2 = 0; kk2 < 2; kk2++) {
                    unsigned b0, b1, b2, b3;
                    ldm_x4(b0, b1, b2, b3, wb + nt * 1152 + kk2 * 64);
                    mma16816f(d4, a[2 * kk2],     b0, b1);
                    mma16816f(d4, a[2 * kk2 + 1], b2, b3);
                }
                const int c = nt * 8 + t4 * 2;
                float bb0 = sd_b1[c], bb1 = sd_b1[c + 1];
                float v0 = fmaxf(d4[0] + bb0, 0.f) + fmaxf(d4[2] + bb0, 0.f);
                float v1 = fmaxf(d4[1] + bb1, 0.f) + fmaxf(d4[3] + bb1, 0.f);
                v0 += __shfl_xor_sync(0xffffffffu, v0, 4);
                v0 += __shfl_xor_sync(0xffffffffu, v0, 8);
                v0 += __shfl_xor_sync(0xffffffffu, v0, 16);
                v1 += __shfl_xor_sync(0xffffffffu, v1, 4);
                v1 += __shfl_xor_sync(0xffffffffu, v1, 8);
                v1 += __shfl_xor_sync(0xffffffffu, v1, 16);
                if (lane < 4) {
                    atomicAdd(&sm->msum[c], v0);
                    atomicAdd(&sm->msum[c + 1], v1);
                }
            }
        }
    }
    __syncthreads();
    if (tid < 128) {
        // contraction over 2cl = 128 dims (sd_w2 is 128x128)
        float r = sd_b2[tid] + sm->accs[tid] * (1.f / 4096.f);
        #pragma unroll 8
        for (int k = 0; k < 128; k++)
            r += (sm->msum[k] * (1.f / 64.f)) * sd_w2[k * 128 + tid];
        out[(size_t)b * 128 + tid] = r;
    }
}

extern "C" void kernel_launch(void* const* d_in, const int* in_sizes, int n_in,
                              void* d_out, int out_size) {
    (void)in_sizes; (void)n_in; (void)out_size;
    cudaFuncSetAttribute(sgh_kernel, cudaFuncAttributeMaxDynamicSharedMemorySize,
                         (int)sizeof(Smem));
    const float* s     = (const float*)d_in[0];
    const float* se_w1 = (const float*)d_in[1];
    const float* se_b1 = (const float*)d_in[2];
    const float* se_w2 = (const float*)d_in[3];
    const float* se_b2 = (const float*)d_in[4];
    const float* sd_w1 = (const float*)d_in[5];
    const float* sd_b1 = (const float*)d_in[6];
    const float* sd_w2 = (const float*)d_in[7];
    const float* sd_b2 = (const float*)d_in[8];
    const float* rc_w1 = (const float*)d_in[9];
    const float* rc_b1 = (const float*)d_in[10];
    const float* rc_w2 = (const float*)d_in[11];
    const float* rc_b2 = (const float*)d_in[12];
    const float* rc_w3 = (const float*)d_in[13];
    const float* rc_b3 = (const float*)d_in[14];
    const float* an_w1 = (const float*)d_in[15];
    const float* an_b1 = (const float*)d_in[16];
    const float* an_w2 = (const float*)d_in[17];
    const float* an_b2 = (const float*)d_in[18];

    sgh_kernel<<<128, NTHREADS, sizeof(Smem)>>>(
        s, se_w1, se_b1, se_w2, se_b2, sd_w1, sd_b1, sd_w2, sd_b2,
        rc_w1, rc_b1, rc_w2, rc_b2, rc_w3, rc_b3,
        an_w1, an_b1, an_w2, an_b2, (float*)d_out);
}

// round 13
// speedup vs baseline: 1.3499x; 1.0240x over previous
#include <cuda_runtime.h>
#include <cuda_fp16.h>

// SimpleGraphHead fused kernel, round 13.
// B=128, N=64, cl=64. One CTA per batch, 12 warps.
// vs r12: vacc accumulators are half2[16] (frees 16 regs -> scheduling
// slack at the 168-reg budget; combine is 1 HADD2 instead of cvt+2 FADD).

#define NWARPS 12
#define NTHREADS 384

struct Smem {
    __half Hh[64][72];       // fp16 H (also Phase-A working buffer), row=144B
    __half P1h[64][136];     // row=272B
    __half P2h[64][136];
    __half Q1h[64][72];      // row=144B
    __half Q2h[64][72];
    __half W2T[128][136];    // overlay region starts here (88 KB)
    __half W3T[128][136];
    __half AW2T[128][72];
    __half w1Lh[128];
    __half aw1Lh[64];
    __half2 b2h2[64];
    __half2 b3h2[64];
    __half2 abh2[64];        // 0.5*an_b2 pairs
    float  hx[64], hy[64];
    float  accs[128];
    float  msum[128];
};

__device__ __forceinline__ __half2 u2h(unsigned u) {
    return *reinterpret_cast<__half2*>(&u);
}
__device__ __forceinline__ unsigned h2u(__half2 h) {
    return *reinterpret_cast<unsigned*>(&h);
}
__device__ __forceinline__ unsigned tanh_h2(unsigned x) {
    unsigned y;
    asm("tanh.approx.f16x2 %0, %1;" : "=r"(y) : "r"(x));
    return y;
}
// f16-accumulate mma
__device__ __forceinline__ void mma16816h(unsigned* d, const unsigned* a,
                                          unsigned b0, unsigned b1) {
    asm volatile(
        "mma.sync.aligned.m16n8k16.row.col.f16.f16.f16.f16 "
        "{%0,%1}, {%2,%3,%4,%5}, {%6,%7}, {%0,%1};\n"
        : "+r"(d[0]), "+r"(d[1])
        : "r"(a[0]), "r"(a[1]), "r"(a[2]), "r"(a[3]), "r"(b0), "r"(b1));
}
// f32-accumulate mma (for table builds)
__device__ __forceinline__ void mma16816f(float* d, const unsigned* a,
                                          unsigned b0, unsigned b1) {
    asm volatile(
        "mma.sync.aligned.m16n8k16.row.col.f32.f16.f16.f32 "
        "{%0,%1,%2,%3}, {%4,%5,%6,%7}, {%8,%9}, {%0,%1,%2,%3};\n"
        : "+f"(d[0]), "+f"(d[1]), "+f"(d[2]), "+f"(d[3])
        : "r"(a[0]), "r"(a[1]), "r"(a[2]), "r"(a[3]), "r"(b0), "r"(b1));
}
__device__ __forceinline__ void ldm_x4(unsigned& r0, unsigned& r1,
                                       unsigned& r2, unsigned& r3,
                                       unsigned saddr) {
    asm volatile("ldmatrix.sync.aligned.m8n8.x4.shared.b16 {%0,%1,%2,%3}, [%4];"
                 : "=r"(r0), "=r"(r1), "=r"(r2), "=r"(r3) : "r"(saddr));
}
__device__ __forceinline__ unsigned frag_fix(unsigned p2f, unsigned d2,
                                             unsigned w, unsigned base,
                                             __half2 z2) {
    __half2 corr = __hfma2(u2h(d2), u2h(w), u2h(base));
    return h2u(__hmax2(__hadd2(u2h(p2f), corr), z2));
}
__device__ __forceinline__ unsigned relu_bias(unsigned acc, __half2 bias,
                                              __half2 z2) {
    return h2u(__hmax2(__hadd2(u2h(acc), bias), z2));
}
// sigmoid(da + ab) = 0.5*tanh(0.5*da + 0.5*ab) + 0.5, all half2
__device__ __forceinline__ __half2 sigmoid_h2(unsigned da, __half2 abp,
                                              __half2 h05) {
    unsigned t = h2u(__hfma2(u2h(da), h05, abp));
    return __hfma2(u2h(tanh_h2(t)), h05, h05);
}

__global__ void __launch_bounds__(NTHREADS, 1)
sgh_kernel(const float* __restrict__ s,
           const float* __restrict__ se_w1, const float* __restrict__ se_b1,
           const float* __restrict__ se_w2, const float* __restrict__ se_b2,
           const float* __restrict__ sd_w1, const float* __restrict__ sd_b1,
           const float* __restrict__ sd_w2, const float* __restrict__ sd_b2,
           const float* __restrict__ rc_w1, const float* __restrict__ rc_b1,
           const float* __restrict__ rc_w2, const float* __restrict__ rc_b2,
           const float* __restrict__ rc_w3, const float* __restrict__ rc_b3,
           const float* __restrict__ an_w1, const float* __restrict__ an_b1,
           const float* __restrict__ an_w2, const float* __restrict__ an_b2,
           float* __restrict__ out) {
    extern __shared__ char smraw[];
    Smem* sm = reinterpret_cast<Smem*>(smraw);
    const int b = blockIdx.x;
    const int tid = threadIdx.x;
    const int warp = tid >> 5;
    const int lane = tid & 31;
    const int g  = lane >> 2;
    const int t4 = lane & 3;
    const int trow = lane & 7;
    const int tileid = lane >> 3;
    const int lrow  = lane & 15;
    const int lcol8 = (lane >> 4) << 3;

    // Overlay region (88 KB spanning W2T/W3T/AW2T)
    char* ovl = reinterpret_cast<char*>(&sm->W2T[0][0]);
    __half* SE1T  = reinterpret_cast<__half*>(ovl);          // [64][72]
    __half* SE2T  = reinterpret_cast<__half*>(ovl + 9216);   // [64][72]
    __half* W1aT  = reinterpret_cast<__half*>(ovl + 18432);  // [128][72]
    __half* W1bT  = reinterpret_cast<__half*>(ovl + 36864);  // [128][72]
    __half* AW1aT = reinterpret_cast<__half*>(ovl + 55296);  // [64][72]
    __half* AW1bT = reinterpret_cast<__half*>(ovl + 64512);  // [64][72]

    // ---------------- Stage everything for Phase A + B ----------------
    const float* sb = s + (size_t)b * 64 * 64;
    for (int idx = tid; idx < 4096; idx += NTHREADS)
        sm->Hh[idx >> 6][idx & 63] = __float2half(sb[idx]);
    for (int idx = tid; idx < 2048; idx += NTHREADS) {
        int k = (idx >> 6) << 1, n = idx & 63;
        *reinterpret_cast<__half2*>(&SE1T[n * 72 + k]) =
            __floats2half2_rn(se_w1[k * 64 + n], se_w1[(k + 1) * 64 + n]);
        *reinterpret_cast<__half2*>(&SE2T[n * 72 + k]) =
            __floats2half2_rn(se_w2[k * 64 + n], se_w2[(k + 1) * 64 + n]);
    }
    for (int idx = tid; idx < 4096; idx += NTHREADS) {
        int k = (idx >> 7) << 1, n = idx & 127;
        *reinterpret_cast<__half2*>(&W1aT[n * 72 + k]) =
            __floats2half2_rn(rc_w1[k * 128 + n], rc_w1[(k + 1) * 128 + n]);
        *reinterpret_cast<__half2*>(&W1bT[n * 72 + k]) =
            __floats2half2_rn(rc_w1[(64 + k) * 128 + n],
                              rc_w1[(65 + k) * 128 + n]);
    }
    for (int idx = tid; idx < 2048; idx += NTHREADS) {
        int k = (idx >> 6) << 1, n = idx & 63;
        *reinterpret_cast<__half2*>(&AW1aT[n * 72 + k]) =
            __floats2half2_rn(an_w1[k * 64 + n], an_w1[(k + 1) * 64 + n]);
        *reinterpret_cast<__half2*>(&AW1bT[n * 72 + k]) =
            __floats2half2_rn(an_w1[(64 + k) * 64 + n],
                              an_w1[(65 + k) * 64 + n]);
    }
    if (tid < 128) {
        sm->w1Lh[tid] = __float2half(rc_w1[128 * 128 + tid]);
        sm->accs[tid] = 0.f;
        sm->msum[tid] = 0.f;
    }
    if (tid < 64) {
        sm->aw1Lh[tid] = __float2half(an_w1[128 * 64 + tid]);
        sm->b2h2[tid] = __floats2half2_rn(rc_b2[2 * tid], rc_b2[2 * tid + 1]);
        sm->b3h2[tid] = __floats2half2_rn(rc_b3[2 * tid], rc_b3[2 * tid + 1]);
        sm->abh2[tid] = __floats2half2_rn(0.5f * an_b2[2 * tid],
                                          0.5f * an_b2[2 * tid + 1]);
    }
    __syncthreads();

    // ---------------- Phase A: state encoder via mma, in-place in Hh ------
    {
        const unsigned ThBase =
            (unsigned)__cvta_generic_to_shared(&sm->Hh[0][0]);
        const int r0 = 16 * (warp & 3);
        const int half = warp >> 2;   // warps 0-7 active (half 0/1)
        const unsigned addrA = ThBase + (r0 + lrow) * 144 + lcol8 * 2;

        #pragma unroll 1
        for (int layer = 0; layer < 2; layer++) {
            const __half* WT = layer ? SE2T : SE1T;
            const float* bias = layer ? se_b2 : se_b1;
            unsigned a[4][4];
            if (warp < 8) {
                #pragma unroll
                for (int kk = 0; kk < 4; kk++)
                    ldm_x4(a[kk][0], a[kk][1], a[kk][2], a[kk][3],
                           addrA + kk * 32);
            }
            __syncthreads();   // all reads of Th done before any store
            if (warp < 8) {
                const unsigned wb = (unsigned)__cvta_generic_to_shared(WT)
                                    + trow * 144 + tileid * 16;
                #pragma unroll
                for (int t = 0; t < 4; t++) {
                    const int nt = half * 4 + t;
                    float d4[4] = {0.f, 0.f, 0.f, 0.f};
                    #pragma unroll
                    for (int kk2 = 0; kk2 < 2; kk2++) {
                        unsigned b0, b1, b2, b3;
                        ldm_x4(b0, b1, b2, b3, wb + nt * 1152 + kk2 * 64);
                        mma16816f(d4, a[2 * kk2],     b0, b1);
                        mma16816f(d4, a[2 * kk2 + 1], b2, b3);
                    }
                    const int c = nt * 8 + t4 * 2;
                    float bb0 = bias[c], bb1 = bias[c + 1];
                    float h0 = fmaxf(d4[0] + bb0, 0.f);
                    float h1 = fmaxf(d4[1] + bb1, 0.f);
                    float h2 = fmaxf(d4[2] + bb0, 0.f);
                    float h3 = fmaxf(d4[3] + bb1, 0.f);
                    *reinterpret_cast<__half2*>(&sm->Hh[r0 + g][c]) =
                        __floats2half2_rn(h0, h1);
                    *reinterpret_cast<__half2*>(&sm->Hh[r0 + g + 8][c]) =
                        __floats2half2_rn(h2, h3);
                    if (layer == 1 && nt == 0 && t4 == 0) {
                        sm->hx[r0 + g] = h0;     sm->hy[r0 + g] = h1;
                        sm->hx[r0 + g + 8] = h2; sm->hy[r0 + g + 8] = h3;
                    }
                }
            }
            __syncthreads();   // stores visible before next layer's reads
        }
    }

    // ---------------- Phase B: P/Q tables via mma ----------------
    {
        const unsigned HhBase = (unsigned)__cvta_generic_to_shared(&sm->Hh[0][0]);
        const int r0 = 16 * (warp & 3);
        const unsigned addrA = HhBase + (r0 + lrow) * 144 + lcol8 * 2;
        unsigned a[4][4];
        #pragma unroll
        for (int kk = 0; kk < 4; kk++)
            ldm_x4(a[kk][0], a[kk][1], a[kk][2], a[kk][3], addrA + kk * 32);

        if (warp < 8) {
            const bool isP1 = (warp < 4);
            const __half* WT = isP1 ? W1aT : W1bT;
            const unsigned wb = (unsigned)__cvta_generic_to_shared(WT)
                                + trow * 144 + tileid * 16;
            __half* dstT = isP1 ? &sm->P1h[0][0] : &sm->P2h[0][0];
            #pragma unroll
            for (int nt = 0; nt < 16; nt++) {
                float d4[4] = {0.f, 0.f, 0.f, 0.f};
                #pragma unroll
                for (int kk2 = 0; kk2 < 2; kk2++) {
                    unsigned b0, b1, b2, b3;
                    ldm_x4(b0, b1, b2, b3, wb + nt * 1152 + kk2 * 64);
                    mma16816f(d4, a[2 * kk2],     b0, b1);
                    mma16816f(d4, a[2 * kk2 + 1], b2, b3);
                }
                const int c = nt * 8 + t4 * 2;
                float bb0 = isP1 ? rc_b1[c] : 0.f;
                float bb1 = isP1 ? rc_b1[c + 1] : 0.f;
                *reinterpret_cast<__half2*>(dstT + (r0 + g) * 136 + c) =
                    __floats2half2_rn(d4[0] + bb0, d4[1] + bb1);
                *reinterpret_cast<__half2*>(dstT + (r0 + g + 8) * 136 + c) =
                    __floats2half2_rn(d4[2] + bb0, d4[3] + bb1);
            }
        } else {
            const unsigned wbA = (unsigned)__cvta_generic_to_shared(AW1aT)
                                 + trow * 144 + tileid * 16;
            const unsigned wbB = (unsigned)__cvta_generic_to_shared(AW1bT)
                                 + trow * 144 + tileid * 16;
            #pragma unroll
            for (int nt = 0; nt < 8; nt++) {
                const int c = nt * 8 + t4 * 2;
                {
                    float d4[4] = {0.f, 0.f, 0.f, 0.f};
                    #pragma unroll
                    for (int kk2 = 0; kk2 < 2; kk2++) {
                        unsigned b0, b1, b2, b3;
                        ldm_x4(b0, b1, b2, b3, wbA + nt * 1152 + kk2 * 64);
                        mma16816f(d4, a[2 * kk2],     b0, b1);
                        mma16816f(d4, a[2 * kk2 + 1], b2, b3);
                    }
                    float bb0 = an_b1[c], bb1 = an_b1[c + 1];
                    *reinterpret_cast<__half2*>(&sm->Q1h[r0 + g][c]) =
                        __floats2half2_rn(d4[0] + bb0, d4[1] + bb1);
                    *reinterpret_cast<__half2*>(&sm->Q1h[r0 + g + 8][c]) =
                        __floats2half2_rn(d4[2] + bb0, d4[3] + bb1);
                }
                {
                    float d4[4] = {0.f, 0.f, 0.f, 0.f};
                    #pragma unroll
                    for (int kk2 = 0; kk2 < 2; kk2++) {
                        unsigned b0, b1, b2, b3;
                        ldm_x4(b0, b1, b2, b3, wbB + nt * 1152 + kk2 * 64);
                        mma16816f(d4, a[2 * kk2],     b0, b1);
                        mma16816f(d4, a[2 * kk2 + 1], b2, b3);
                    }
                    *reinterpret_cast<__half2*>(&sm->Q2h[r0 + g][c]) =
                        __floats2half2_rn(d4[0], d4[1]);
                    *reinterpret_cast<__half2*>(&sm->Q2h[r0 + g + 8][c]) =
                        __floats2half2_rn(d4[2], d4[3]);
                }
            }
        }
    }
    __syncthreads();

    // ---------------- Stage main-loop weights (overwrites overlay) --------
    for (int idx = tid; idx < 8192; idx += NTHREADS) {
        int k = (idx >> 7) << 1, n = idx & 127;
        *reinterpret_cast<__half2*>(&sm->W2T[n][k]) =
            __floats2half2_rn(rc_w2[k * 128 + n], rc_w2[(k + 1) * 128 + n]);
        *reinterpret_cast<__half2*>(&sm->W3T[n][k]) =
            __floats2half2_rn(rc_w3[k * 128 + n], rc_w3[(k + 1) * 128 + n]);
    }
    for (int idx = tid; idx < 4096; idx += NTHREADS) {
        int k = (idx >> 7) << 1, n = idx & 127;
        *reinterpret_cast<__half2*>(&sm->AW2T[n][k]) =
            __floats2half2_rn(an_w2[k * 128 + n], an_w2[(k + 1) * 128 + n]);
    }
    __syncthreads();

    // ---------------- Main loop: 32-pair slabs ----------------
    const unsigned baseW2 = (unsigned)__cvta_generic_to_shared(&sm->W2T[0][0])
                            + trow * 272 + tileid * 16;
    const unsigned baseW3 = (unsigned)__cvta_generic_to_shared(&sm->W3T[0][0])
                            + trow * 272 + tileid * 16;
    const unsigned baseAW = (unsigned)__cvta_generic_to_shared(&sm->AW2T[0][0])
                            + trow * 144 + tileid * 16;
    const unsigned baseP2 = (unsigned)__cvta_generic_to_shared(&sm->P2h[0][0])
                            + lrow * 272 + lcol8 * 2;
    const unsigned baseQ2 = (unsigned)__cvta_generic_to_shared(&sm->Q2h[0][0])
                            + lrow * 144 + lcol8 * 2;

    const __half2 z2 = __floats2half2_rn(0.f, 0.f);
    const __half2 h05 = __floats2half2_rn(0.5f, 0.5f);

    unsigned af2lo[8][4], af2hi[8][4];   // GEMM1 accumulators, then x2 frags
    unsigned afQlo[4][4], afQhi[4][4];
    __half2 vacch[16];
    #pragma unroll
    for (int nt = 0; nt < 16; nt++) vacch[nt] = z2;

    for (int slab = warp; slab < 128; slab += NWARPS) {
        const int i0 = (slab >> 2) << 1;
        const int i1 = i0 + 1;
        const int j0 = (slab & 3) << 4;
        const int jA = j0 + g;
        const int jB = jA + 8;

        const float hxA = sm->hx[jA], hyA = sm->hy[jA];
        const float hxB = sm->hx[jB], hyB = sm->hy[jB];
        const float xi0 = sm->hx[i0], yi0 = sm->hy[i0];
        const float xi1 = sm->hx[i1], yi1 = sm->hy[i1];
        const unsigned dA0 = h2u(__float2half2_rn(
            (xi0 - hxA) * (xi0 - hxA) + (yi0 - hyA) * (yi0 - hyA)));
        const unsigned dB0 = h2u(__float2half2_rn(
            (xi0 - hxB) * (xi0 - hxB) + (yi0 - hyB) * (yi0 - hyB)));
        const unsigned dA1 = h2u(__float2half2_rn(
            (xi1 - hxA) * (xi1 - hxA) + (yi1 - hyA) * (yi1 - hyA)));
        const unsigned dB1 = h2u(__float2half2_rn(
            (xi1 - hxB) * (xi1 - hxB) + (yi1 - hyB) * (yi1 - hyB)));

        const unsigned addrP2 = baseP2 + j0 * 272;
        const unsigned addrQ2 = baseQ2 + j0 * 144;
        const __half* P1a = sm->P1h[i0];
        const __half* P1b = sm->P1h[i1];
        const __half* Q1a = sm->Q1h[i0];
        const __half* Q1b = sm->Q1h[i1];

        // ---- GEMM1, K-split output-stationary ----
        #pragma unroll
        for (int p = 0; p < 8; p++) {
            af2lo[p][0] = af2lo[p][1] = af2lo[p][2] = af2lo[p][3] = 0u;
            af2hi[p][0] = af2hi[p][1] = af2hi[p][2] = af2hi[p][3] = 0u;
        }
        #pragma unroll
        for (int h = 0; h < 2; h++) {
            unsigned afl[4][4], afh[4][4];
            #pragma unroll
            for (int l = 0; l < 4; l++) {
                const int kk = 4 * h + l;
                const int c = kk * 16 + t4 * 2;
                unsigned w01 = *reinterpret_cast<const unsigned*>(&sm->w1Lh[c]);
                unsigned w89 = *reinterpret_cast<const unsigned*>(&sm->w1Lh[c + 8]);
                unsigned pa01 = *reinterpret_cast<const unsigned*>(&P1a[c]);
                unsigned pa89 = *reinterpret_cast<const unsigned*>(&P1a[c + 8]);
                unsigned pb01 = *reinterpret_cast<const unsigned*>(&P1b[c]);
                unsigned pb89 = *reinterpret_cast<const unsigned*>(&P1b[c + 8]);
                unsigned f0, f1, f2, f3;
                ldm_x4(f0, f1, f2, f3, addrP2 + kk * 32);
                afl[l][0] = frag_fix(f0, dA0, w01, pa01, z2);
                afl[l][1] = frag_fix(f1, dB0, w01, pa01, z2);
                afl[l][2] = frag_fix(f2, dA0, w89, pa89, z2);
                afl[l][3] = frag_fix(f3, dB0, w89, pa89, z2);
                afh[l][0] = frag_fix(f0, dA1, w01, pb01, z2);
                afh[l][1] = frag_fix(f1, dB1, w01, pb01, z2);
                afh[l][2] = frag_fix(f2, dA1, w89, pb89, z2);
                afh[l][3] = frag_fix(f3, dB1, w89, pb89, z2);
            }
            #pragma unroll
            for (int s2 = 0; s2 < 16; s2++) {
                unsigned* dlo = &af2lo[s2 >> 1][(s2 & 1) * 2];
                unsigned* dhi = &af2hi[s2 >> 1][(s2 & 1) * 2];
                #pragma unroll
                for (int q = 0; q < 2; q++) {
                    const int kk2 = 2 * h + q;
                    unsigned a0, a1, a2, a3;
                    ldm_x4(a0, a1, a2, a3, baseW2 + s2 * 2176 + kk2 * 64);
                    mma16816h(dlo, afl[2 * q],     a0, a1);
                    mma16816h(dlo, afl[2 * q + 1], a2, a3);
                    mma16816h(dhi, afh[2 * q],     a0, a1);
                    mma16816h(dhi, afh[2 * q + 1], a2, a3);
                }
            }
        }
        // in-place bias + relu -> x2 fragments
        #pragma unroll
        for (int p = 0; p < 8; p++) {
            const __half2 b2a = sm->b2h2[p * 8 + t4];
            const __half2 b2b = sm->b2h2[p * 8 + 4 + t4];
            af2lo[p][0] = relu_bias(af2lo[p][0], b2a, z2);
            af2lo[p][1] = relu_bias(af2lo[p][1], b2a, z2);
            af2lo[p][2] = relu_bias(af2lo[p][2], b2b, z2);
            af2lo[p][3] = relu_bias(af2lo[p][3], b2b, z2);
            af2hi[p][0] = relu_bias(af2hi[p][0], b2a, z2);
            af2hi[p][1] = relu_bias(af2hi[p][1], b2a, z2);
            af2hi[p][2] = relu_bias(af2hi[p][2], b2b, z2);
            af2hi[p][3] = relu_bias(af2hi[p][3], b2b, z2);
        }

        // ---- att layer-1 fragments (shared Q2 loads) ----
        #pragma unroll
        for (int kk = 0; kk < 4; kk++) {
            const int c = kk * 16 + t4 * 2;
            unsigned w01 = *reinterpret_cast<const unsigned*>(&sm->aw1Lh[c]);
            unsigned w89 = *reinterpret_cast<const unsigned*>(&sm->aw1Lh[c + 8]);
            unsigned qa01 = *reinterpret_cast<const unsigned*>(&Q1a[c]);
            unsigned qa89 = *reinterpret_cast<const unsigned*>(&Q1a[c + 8]);
            unsigned qb01 = *reinterpret_cast<const unsigned*>(&Q1b[c]);
            unsigned qb89 = *reinterpret_cast<const unsigned*>(&Q1b[c + 8]);
            unsigned f0, f1, f2, f3;
            ldm_x4(f0, f1, f2, f3, addrQ2 + kk * 32);
            afQlo[kk][0] = frag_fix(f0, dA0, w01, qa01, z2);
            afQlo[kk][1] = frag_fix(f1, dB0, w01, qa01, z2);
            afQlo[kk][2] = frag_fix(f2, dA0, w89, qa89, z2);
            afQlo[kk][3] = frag_fix(f3, dB0, w89, qa89, z2);
            afQhi[kk][0] = frag_fix(f0, dA1, w01, qb01, z2);
            afQhi[kk][1] = frag_fix(f1, dB1, w01, qb01, z2);
            afQhi[kk][2] = frag_fix(f2, dA1, w89, qb89, z2);
            afQhi[kk][3] = frag_fix(f3, dB1, w89, qb89, z2);
        }

        // ---- fused GEMM2 + att + half2 sigmoid/combine -> vacch ----
        #pragma unroll
        for (int nt = 0; nt < 16; nt++) {
            unsigned drlo[2] = {0u, 0u}, drhi[2] = {0u, 0u};
            #pragma unroll
            for (int kk2 = 0; kk2 < 4; kk2++) {
                unsigned r0, r1, r2, r3;
                ldm_x4(r0, r1, r2, r3, baseW3 + nt * 2176 + kk2 * 64);
                mma16816h(drlo, af2lo[2 * kk2],     r0, r1);
                mma16816h(drlo, af2lo[2 * kk2 + 1], r2, r3);
                mma16816h(drhi, af2hi[2 * kk2],     r0, r1);
                mma16816h(drhi, af2hi[2 * kk2 + 1], r2, r3);
            }
            unsigned dalo[2] = {0u, 0u}, dahi[2] = {0u, 0u};
            #pragma unroll
            for (int kk2 = 0; kk2 < 2; kk2++) {
                unsigned r0, r1, r2, r3;
                ldm_x4(r0, r1, r2, r3, baseAW + nt * 1152 + kk2 * 64);
                mma16816h(dalo, afQlo[2 * kk2],     r0, r1);
                mma16816h(dalo, afQlo[2 * kk2 + 1], r2, r3);
                mma16816h(dahi, afQhi[2 * kk2],     r0, r1);
                mma16816h(dahi, afQhi[2 * kk2 + 1], r2, r3);
            }
            const __half2 b3p = sm->b3h2[nt * 4 + t4];
            const __half2 abp = sm->abh2[nt * 4 + t4];
            __half2 sA = sigmoid_h2(dalo[0], abp, h05);
            __half2 sB = sigmoid_h2(dalo[1], abp, h05);
            __half2 sC = sigmoid_h2(dahi[0], abp, h05);
            __half2 sD = sigmoid_h2(dahi[1], abp, h05);
            __half2 rA = __hmax2(__hadd2(u2h(drlo[0]), b3p), z2);
            __half2 rB = __hmax2(__hadd2(u2h(drlo[1]), b3p), z2);
            __half2 rC = __hmax2(__hadd2(u2h(drhi[0]), b3p), z2);
            __half2 rD = __hmax2(__hadd2(u2h(drhi[1]), b3p), z2);
            __half2 vh = __hmul2(rA, sA);
            vh = __hfma2(rB, sB, vh);
            vh = __hfma2(rC, sC, vh);
            vh = __hfma2(rD, sD, vh);
            vacch[nt] = __hadd2(vacch[nt], vh);
        }
    }

    // ---- one reduction per warp ----
    #pragma unroll
    for (int nt = 0; nt < 16; nt++) {
        float2 vf = __half22float2(vacch[nt]);
        float v0 = vf.x, v1 = vf.y;
        v0 += __shfl_xor_sync(0xffffffffu, v0, 4);
        v0 += __shfl_xor_sync(0xffffffffu, v0, 8);
        v0 += __shfl_xor_sync(0xffffffffu, v0, 16);
        v1 += __shfl_xor_sync(0xffffffffu, v1, 4);
        v1 += __shfl_xor_sync(0xffffffffu, v1, 8);
        v1 += __shfl_xor_sync(0xffffffffu, v1, 16);
        if (lane < 4) {
            atomicAdd(&sm->accs[nt * 8 + lane * 2], v0);
            atomicAdd(&sm->accs[nt * 8 + lane * 2 + 1], v1);
        }
    }
    __syncthreads();

    // ---------------- Epilogue: self_dyn layer-1 via mma ----------------
    {
        __half* SW1T = reinterpret_cast<__half*>(ovl);  // [128][72] over W2T
        for (int idx = tid; idx < 4096; idx += NTHREADS) {
            int k = (idx >> 7) << 1, n = idx & 127;
            *reinterpret_cast<__half2*>(&SW1T[n * 72 + k]) =
                __floats2half2_rn(sd_w1[k * 128 + n], sd_w1[(k + 1) * 128 + n]);
        }
        __syncthreads();
        if (warp < 4) {
            const unsigned HhBase =
                (unsigned)__cvta_generic_to_shared(&sm->Hh[0][0]);
            const int r0 = 16 * warp;
            const unsigned addrA = HhBase + (r0 + lrow) * 144 + lcol8 * 2;
            unsigned a[4][4];
            #pragma unroll
            for (int kk = 0; kk < 4; kk++)
                ldm_x4(a[kk][0], a[kk][1], a[kk][2], a[kk][3], addrA + kk * 32);
            const unsigned wb = (unsigned)__cvta_generic_to_shared(SW1T)
                                + trow * 144 + tileid * 16;
            #pragma unroll
            for (int nt = 0; nt < 16; nt++) {
                float d4[4] = {0.f, 0.f, 0.f, 0.f};
                #pragma unroll
                for (int kk2 = 0; kk2 < 2; kk2++) {
                    unsigned b0, b1, b2, b3;
                    ldm_x4(b0, b1, b2, b3, wb + nt * 1152 + kk2 * 64);
                    mma16816f(d4, a[2 * kk2],     b0, b1);
                    mma16816f(d4, a[2 * kk2 + 1], b2, b3);
                }
                const int c = nt * 8 + t4 * 2;
                float bb0 = sd_b1[c], bb1 = sd_b1[c + 1];
                float v0 = fmaxf(d4[0] + bb0, 0.f) + fmaxf(d4[2] + bb0, 0.f);
                float v1 = fmaxf(d4[1] + bb1, 0.f) + fmaxf(d4[3] + bb1, 0.f);
                v0 += __shfl_xor_sync(0xffffffffu, v0, 4);
                v0 += __shfl_xor_sync(0xffffffffu, v0, 8);
                v0 += __shfl_xor_sync(0xffffffffu, v0, 16);
                v1 += __shfl_xor_sync(0xffffffffu, v1, 4);
                v1 += __shfl_xor_sync(0xffffffffu, v1, 8);
                v1 += __shfl_xor_sync(0xffffffffu, v1, 16);
                if (lane < 4) {
                    atomicAdd(&sm->msum[c], v0);
                    atomicAdd(&sm->msum[c + 1], v1);
                }
            }
        }
    }
    __syncthreads();
    if (tid < 128) {
        // contraction over 2cl = 128 dims (sd_w2 is 128x128)
        float r = sd_b2[tid] + sm->accs[tid] * (1.f / 4096.f);
        #pragma unroll 8
        for (int k = 0; k < 128; k++)
            r += (sm->msum[k] * (1.f / 64.f)) * sd_w2[k * 128 + tid];
        out[(size_t)b * 128 + tid] = r;
    }
}

extern "C" void kernel_launch(void* const* d_in, const int* in_sizes, int n_in,
                              void* d_out, int out_size) {
    (void)in_sizes; (void)n_in; (void)out_size;
    cudaFuncSetAttribute(sgh_kernel, cudaFuncAttributeMaxDynamicSharedMemorySize,
                         (int)sizeof(Smem));
    const float* s     = (const float*)d_in[0];
    const float* se_w1 = (const float*)d_in[1];
    const float* se_b1 = (const float*)d_in[2];
    const float* se_w2 = (const float*)d_in[3];
    const float* se_b2 = (const float*)d_in[4];
    const float* sd_w1 = (const float*)d_in[5];
    const float* sd_b1 = (const float*)d_in[6];
    const float* sd_w2 = (const float*)d_in[7];
    const float* sd_b2 = (const float*)d_in[8];
    const float* rc_w1 = (const float*)d_in[9];
    const float* rc_b1 = (const float*)d_in[10];
    const float* rc_w2 = (const float*)d_in[11];
    const float* rc_b2 = (const float*)d_in[12];
    const float* rc_w3 = (const float*)d_in[13];
    const float* rc_b3 = (const float*)d_in[14];
    const float* an_w1 = (const float*)d_in[15];
    const float* an_b1 = (const float*)d_in[16];
    const float* an_w2 = (const float*)d_in[17];
    const float* an_b2 = (const float*)d_in[18];

    sgh_kernel<<<128, NTHREADS, sizeof(Smem)>>>(
        s, se_w1, se_b1, se_w2, se_b2, sd_w1, sd_b1, sd_w2, sd_b2,
        rc_w1, rc_b1, rc_w2, rc_b2, rc_w3, rc_b3,
        an_w1, an_b1, an_w2, an_b2, (float*)d_out);
}